// round 4
// baseline (speedup 1.0000x reference)
#include <cuda_runtime.h>
#include <cuda_bf16.h>

#define KDIM 8
static const int MAXN = 100000;
static const int MAXE = 3200000;

// ---- scratch (device globals; no cudaMalloc allowed) ----
__device__ int    g_count[MAXN];          // per-dst degree histogram
__device__ int    g_rank[MAXE];           // rank of edge within its dst bin
__device__ int    g_off[MAXN + 1];        // bin offsets (exclusive scan)
__device__ int    g_blocklocal[MAXN];     // exclusive scan within scan-block
__device__ int    g_blocksum[128];        // per-scan-block totals (<=98 used)
__device__ int    g_blockbase[128];       // exclusive scan of block sums
__device__ float4 g_pay[2 * MAXE];        // sorted payload: [2p]=rel_q, [2p+1]={w,src,-,-}

// ---------------------------------------------------------------------------
// P1: histogram + rank.  rank[e] = old count of dst[e].
// ---------------------------------------------------------------------------
__global__ void k_hist(const int* __restrict__ edge_dst, int E)
{
    int e = blockIdx.x * blockDim.x + threadIdx.x;
    if (e >= E) return;
    int d = __ldg(edge_dst + e);
    g_rank[e] = atomicAdd(&g_count[d], 1);
}

// ---------------------------------------------------------------------------
// P2a: per-1024-block exclusive scan of g_count; emit block totals.
// ---------------------------------------------------------------------------
__global__ void k_scanA(int N)
{
    int i = blockIdx.x * 1024 + threadIdx.x;
    int lane = threadIdx.x & 31, wid = threadIdx.x >> 5;
    int v = (i < N) ? g_count[i] : 0;
    int x = v;
    #pragma unroll
    for (int o = 1; o < 32; o <<= 1) {
        int y = __shfl_up_sync(0xffffffffu, x, o);
        if (lane >= o) x += y;
    }
    __shared__ int wsum[32];
    if (lane == 31) wsum[wid] = x;
    __syncthreads();
    if (wid == 0) {
        int s = wsum[lane];
        #pragma unroll
        for (int o = 1; o < 32; o <<= 1) {
            int y = __shfl_up_sync(0xffffffffu, s, o);
            if (lane >= o) s += y;
        }
        wsum[lane] = s;
    }
    __syncthreads();
    int incl = x + (wid > 0 ? wsum[wid - 1] : 0);
    if (i < N) g_blocklocal[i] = incl - v;
    if (threadIdx.x == 1023) g_blocksum[blockIdx.x] = incl;
}

// ---------------------------------------------------------------------------
// P2b: exclusive scan of <=128 block sums (single block of 128 threads).
// ---------------------------------------------------------------------------
__global__ void k_scanB(int nb)
{
    int t = threadIdx.x;                  // 128 threads
    int lane = t & 31, wid = t >> 5;
    int v = (t < nb) ? g_blocksum[t] : 0;
    int x = v;
    #pragma unroll
    for (int o = 1; o < 32; o <<= 1) {
        int y = __shfl_up_sync(0xffffffffu, x, o);
        if (lane >= o) x += y;
    }
    __shared__ int wsum[4];
    if (lane == 31) wsum[wid] = x;
    __syncthreads();
    int base = 0;
    for (int wprev = 0; wprev < wid; wprev++) base += wsum[wprev];
    int incl = x + base;
    if (t < nb) g_blockbase[t] = incl - v;
}

// ---------------------------------------------------------------------------
// P2c: materialize g_off[i] = global exclusive prefix; g_off[N] = E.
// ---------------------------------------------------------------------------
__global__ void k_scanC(int N, int E)
{
    int i = blockIdx.x * blockDim.x + threadIdx.x;
    if (i > N) return;
    g_off[i] = (i < N) ? (g_blockbase[i >> 10] + g_blocklocal[i]) : E;
}

// ---------------------------------------------------------------------------
// P3: scatter payload into dst-sorted order (32B aligned stores, no atomics).
// ---------------------------------------------------------------------------
__global__ void k_scatter(const float4* __restrict__ edge_rel_q,
                          const float*  __restrict__ edge_w,
                          const int*    __restrict__ edge_src,
                          const int*    __restrict__ edge_dst,
                          int E)
{
    int e = blockIdx.x * blockDim.x + threadIdx.x;
    if (e >= E) return;
    int d   = __ldg(edge_dst + e);
    int pos = g_off[d] + g_rank[e];
    float4 rq = __ldg(edge_rel_q + e);
    float  w  = __ldg(edge_w + e);
    int    s  = __ldg(edge_src + e);
    g_pay[2 * pos]     = rq;
    g_pay[2 * pos + 1] = make_float4(w, __int_as_float(s), 0.f, 0.f);
}

// ---------------------------------------------------------------------------
// P4: gather-reduce. One warp per node. lane = (j, k): k = lane&7 feature,
// j = lane>>3 edge-subgroup. 2x unrolled: 8 edges in flight per warp iter,
// independent accumulator sets, self-term loads hoisted.
// ---------------------------------------------------------------------------
__global__ void k_reduce(const float*  __restrict__ node_levels,
                         const float4* __restrict__ node_q,
                         float4* __restrict__ out_q,
                         float*  __restrict__ out_l,
                         int N)
{
    int gw   = (blockIdx.x * blockDim.x + threadIdx.x) >> 5;   // node id
    int lane = threadIdx.x & 31;
    if (gw >= N) return;                                       // whole warp exits
    int k = lane & 7;
    int j = lane >> 3;

    int beg = g_off[gw];
    int end = g_off[gw + 1];

    // hoist self-term loads (latency overlaps the loop)
    int ni = gw * KDIM + k;
    float  l_self = __ldg(node_levels + ni);
    float4 q_self = __ldg(node_q + ni);

    float awA = 0.f, axA = 0.f, ayA = 0.f, azA = 0.f, adA = 0.f, alA = 0.f;
    float awB = 0.f, axB = 0.f, ayB = 0.f, azB = 0.f, adB = 0.f, alB = 0.f;

    for (int i = beg + j; i < end; i += 8) {
        int  iB = i + 4;
        bool vB = (iB < end);
        int  iBc = vB ? iB : i;                  // clamp for safe loads

        // issue all payload loads up front (4 independent 16B loads)
        float4 rqA = __ldg(&g_pay[2 * i]);
        float4 wsA = __ldg(&g_pay[2 * i + 1]);
        float4 rqB = __ldg(&g_pay[2 * iBc]);
        float4 wsB = __ldg(&g_pay[2 * iBc + 1]);

        int sA = __float_as_int(wsA.y);
        int sB = __float_as_int(wsB.y);
        int siA = sA * KDIM + k;
        int siB = sB * KDIM + k;

        // issue all node gathers up front (4 independent loads)
        float4 qA = __ldg(node_q + siA);
        float  lA = __ldg(node_levels + siA);
        float4 qB = __ldg(node_q + siB);
        float  lB = __ldg(node_levels + siB);

        float eeA = __expf(8.0f * wsA.x * lA);
        float eeB = vB ? __expf(8.0f * wsB.x * lB) : 0.f;  // mask kills all B terms

        {   // Hamilton product rel_q (*) q_src ; storage (w,x,y,z)
            float w1 = rqA.x, x1 = rqA.y, y1 = rqA.z, z1 = rqA.w;
            float w2 = qA.x,  x2 = qA.y,  y2 = qA.z,  z2 = qA.w;
            awA += eeA * (w1*w2 - x1*x2 - y1*y2 - z1*z2);
            axA += eeA * (w1*x2 + x1*w2 + y1*z2 - z1*y2);
            ayA += eeA * (w1*y2 - x1*z2 + y1*w2 + z1*x2);
            azA += eeA * (w1*z2 + x1*y2 - y1*x2 + z1*w2);
            adA += eeA;
            alA += eeA * lA;
        }
        {
            float w1 = rqB.x, x1 = rqB.y, y1 = rqB.z, z1 = rqB.w;
            float w2 = qB.x,  x2 = qB.y,  y2 = qB.z,  z2 = qB.w;
            awB += eeB * (w1*w2 - x1*x2 - y1*y2 - z1*z2);
            axB += eeB * (w1*x2 + x1*w2 + y1*z2 - z1*y2);
            ayB += eeB * (w1*y2 - x1*z2 + y1*w2 + z1*x2);
            azB += eeB * (w1*z2 + x1*y2 - y1*x2 + z1*w2);
            adB += eeB;
            alB += eeB * lB;
        }
    }

    float aw = awA + awB, ax = axA + axB, ay = ayA + ayB;
    float az = azA + azB, aden = adA + adB, al = alA + alB;

    // reduce over j (lanes with equal k are 8 apart): xor 8, xor 16
    #pragma unroll
    for (int o = 8; o < 32; o <<= 1) {
        aw   += __shfl_xor_sync(0xffffffffu, aw,   o);
        ax   += __shfl_xor_sync(0xffffffffu, ax,   o);
        ay   += __shfl_xor_sync(0xffffffffu, ay,   o);
        az   += __shfl_xor_sync(0xffffffffu, az,   o);
        aden += __shfl_xor_sync(0xffffffffu, aden, o);
        al   += __shfl_xor_sync(0xffffffffu, al,   o);
    }

    if (j == 0) {
        float es = __expf(8.0f * l_self);          // self term (w = 1)
        aw += es * q_self.x;  ax += es * q_self.y;
        ay += es * q_self.z;  az += es * q_self.w;
        aden += es;           al += es * l_self;

        float inv = 1.0f / aden;
        float qw = aw * inv, qx = ax * inv, qy = ay * inv, qz = az * inv;
        float nrm = sqrtf(qw*qw + qx*qx + qy*qy + qz*qz);
        float r   = 1.0f / fmaxf(nrm, 1e-12f);
        out_q[ni] = make_float4(qw * r, qx * r, qy * r, qz * r);
        out_l[ni] = al * inv;
    }
}

// ---------------------------------------------------------------------------
// Launch. Inputs: 0 node_levels [N,K], 1 node_q [N,K,4], 2 edge_rel_q [E,4],
//                 3 edge_w [E], 4 edge_src [E], 5 edge_dst [E].
// Output: q [N,K,4] flattened, then out_levels [N,K].
// ---------------------------------------------------------------------------
extern "C" void kernel_launch(void* const* d_in, const int* in_sizes, int n_in,
                              void* d_out, int out_size)
{
    const float*  node_levels = (const float*) d_in[0];
    const float4* node_q      = (const float4*)d_in[1];
    const float4* edge_rel_q  = (const float4*)d_in[2];
    const float*  edge_w      = (const float*) d_in[3];
    const int*    edge_src    = (const int*)   d_in[4];
    const int*    edge_dst    = (const int*)   d_in[5];

    int NK = in_sizes[0];
    int N  = NK / KDIM;
    int E  = in_sizes[3];

    float4* out_q = (float4*)d_out;
    float*  out_l = (float*)d_out + (long long)NK * 4;

    void* pCount = nullptr;
    cudaGetSymbolAddress(&pCount, g_count);
    cudaMemsetAsync(pCount, 0, (size_t)N * sizeof(int), 0);

    const int TPB = 256;
    int nb = (N + 1023) / 1024;                    // scan blocks (<=98)

    k_hist   <<<(E + TPB - 1) / TPB, TPB>>>(edge_dst, E);
    k_scanA  <<<nb, 1024>>>(N);
    k_scanB  <<<1, 128>>>(nb);
    k_scanC  <<<(N + 1 + TPB - 1) / TPB, TPB>>>(N, E);
    k_scatter<<<(E + TPB - 1) / TPB, TPB>>>(edge_rel_q, edge_w, edge_src,
                                            edge_dst, E);
    k_reduce <<<(N * 32 + TPB - 1) / TPB, TPB>>>(node_levels, node_q,
                                                 out_q, out_l, N);
}

// round 5
// speedup vs baseline: 1.2947x; 1.2947x over previous
#include <cuda_runtime.h>
#include <cuda_bf16.h>

#define KDIM 8
static const int MAXN  = 100000;
static const int MAXNK = MAXN * KDIM;

// Scratch accumulators (device globals — zero-initialized at module load;
// spt_final_kernel re-zeros them after reading so every replay starts clean).
__device__ float4 g_accQ4[MAXNK];   // sum exp_e * accu_q  (w,x,y,z)
__device__ float2 g_accDL2[MAXNK];  // { sum exp_e , sum exp_e * l_src }

// ---------------------------------------------------------------------------
// Edge scatter. One thread per (edge, k); 8 consecutive lanes share one edge
// -> broadcast edge loads, full-128B-line node_q gathers.
// DL pairs via shfl: even-k lanes issue one v4 RED covering two k's.
// DL RED issued before the Hamilton product to overlap LSU queue with FMAs.
// ---------------------------------------------------------------------------
__global__ void __launch_bounds__(256)
spt_edge_kernel(const float*  __restrict__ node_levels,
                const float4* __restrict__ node_q,
                const float4* __restrict__ edge_rel_q,
                const float*  __restrict__ edge_w,
                const int*    __restrict__ edge_src,
                const int*    __restrict__ edge_dst,
                long long EK)
{
    long long t = (long long)blockIdx.x * blockDim.x + threadIdx.x;
    bool active = (t < EK);
    long long tc = active ? t : 0;        // clamp for safe loads
    int e = (int)(tc >> 3);
    int k = (int)(tc & 7);

    int   s  = __ldg(edge_src + e);
    int   d  = __ldg(edge_dst + e);
    float w  = __ldg(edge_w + e);
    float4 rq = __ldg(edge_rel_q + e);

    int si = s * KDIM + k;
    float4 qs = __ldg(node_q + si);
    float  l  = __ldg(node_levels + si);

    float ee  = __expf(8.0f * w * l);     // exp_e (softmax shift cancels)
    float eel = ee * l;

    // Pair up DL values: even lane k takes lane k+1's {ee, eel}.
    float nee  = __shfl_down_sync(0xffffffffu, ee, 1);
    float neel = __shfl_down_sync(0xffffffffu, eel, 1);

    int di = d * KDIM + k;

    // Issue DL RED early (independent of the Hamilton product below).
    if (active && ((k & 1) == 0)) {
        float4* adl = (float4*)(g_accDL2 + di);  // 16B aligned (di even)
        asm volatile("red.global.add.v4.f32 [%0], {%1, %2, %3, %4};"
                     :: "l"(adl), "f"(ee), "f"(eel), "f"(nee), "f"(neel)
                     : "memory");
    }

    // Hamilton product rel_q (*) q_src ; storage order (w,x,y,z)
    float w1 = rq.x, x1 = rq.y, y1 = rq.z, z1 = rq.w;
    float w2 = qs.x, x2 = qs.y, y2 = qs.z, z2 = qs.w;
    float ow = w1*w2 - x1*x2 - y1*y2 - z1*z2;
    float ox = w1*x2 + x1*w2 + y1*z2 - z1*y2;
    float oy = w1*y2 - x1*z2 + y1*w2 + z1*x2;
    float oz = w1*z2 + x1*y2 - y1*x2 + z1*w2;

    if (active) {
        float4* aq = g_accQ4 + di;
        asm volatile("red.global.add.v4.f32 [%0], {%1, %2, %3, %4};"
                     :: "l"(aq), "f"(ee*ow), "f"(ee*ox), "f"(ee*oy), "f"(ee*oz)
                     : "memory");
    }
}

// ---------------------------------------------------------------------------
// Finalize: add self term, divide, L2-normalize, write output, and RE-ZERO
// the accumulators for the next graph replay.
// ---------------------------------------------------------------------------
__global__ void __launch_bounds__(256)
spt_final_kernel(const float* __restrict__ node_levels,
                 const float4* __restrict__ node_q,
                 float4* __restrict__ out_q,
                 float*  __restrict__ out_l,
                 int NK)
{
    int i = blockIdx.x * blockDim.x + threadIdx.x;
    if (i >= NK) return;

    float  l  = node_levels[i];
    float  es = __expf(8.0f * l);         // self term exp (w = 1)
    float4 q  = node_q[i];

    float2 dl = g_accDL2[i];
    float4 a  = g_accQ4[i];

    // re-zero for the next replay (deterministic state at every launch start)
    g_accDL2[i] = make_float2(0.f, 0.f);
    g_accQ4[i]  = make_float4(0.f, 0.f, 0.f, 0.f);

    float denom = dl.x + es;
    float suml  = dl.y + es * l;

    float qw = a.x + es * q.x;
    float qx = a.y + es * q.y;
    float qy = a.z + es * q.z;
    float qz = a.w + es * q.w;

    float inv = 1.0f / denom;
    qw *= inv; qx *= inv; qy *= inv; qz *= inv;

    float nrm = sqrtf(qw*qw + qx*qx + qy*qy + qz*qz);
    float r   = 1.0f / fmaxf(nrm, 1e-12f);
    out_q[i] = make_float4(qw * r, qx * r, qy * r, qz * r);
    out_l[i] = suml * inv;
}

// ---------------------------------------------------------------------------
// Launch. Inputs: 0 node_levels [N,K], 1 node_q [N,K,4], 2 edge_rel_q [E,4],
//                 3 edge_w [E], 4 edge_src [E], 5 edge_dst [E].
// Output: q [N,K,4] flattened, then out_levels [N,K].
// ---------------------------------------------------------------------------
extern "C" void kernel_launch(void* const* d_in, const int* in_sizes, int n_in,
                              void* d_out, int out_size)
{
    const float*  node_levels = (const float*) d_in[0];
    const float4* node_q      = (const float4*)d_in[1];
    const float4* edge_rel_q  = (const float4*)d_in[2];
    const float*  edge_w      = (const float*) d_in[3];
    const int*    edge_src    = (const int*)   d_in[4];
    const int*    edge_dst    = (const int*)   d_in[5];

    int NK = in_sizes[0];                 // N*K
    int E  = in_sizes[3];
    long long EK = (long long)E * KDIM;

    float4* out_q = (float4*)d_out;
    float*  out_l = (float*)d_out + (long long)NK * 4;

    const int TPB = 256;
    int grid_nk = (NK + TPB - 1) / TPB;
    int grid_ek = (int)((EK + TPB - 1) / TPB);

    spt_edge_kernel<<<grid_ek, TPB>>>(node_levels, node_q, edge_rel_q,
                                      edge_w, edge_src, edge_dst, EK);
    spt_final_kernel<<<grid_nk, TPB>>>(node_levels, node_q, out_q, out_l, NK);
}

// round 6
// speedup vs baseline: 1.3761x; 1.0629x over previous
#include <cuda_runtime.h>
#include <cuda_bf16.h>

#define KDIM 8
static const int MAXN  = 100000;
static const int MAXNK = MAXN * KDIM;

// Scratch accumulators (device globals — no cudaMalloc allowed).
__device__ float4 g_accQ4[MAXNK];   // sum exp_e * accu_q  (w,x,y,z)
__device__ float2 g_accDL2[MAXNK];  // { sum exp_e , sum exp_e * l_src }

// ---------------------------------------------------------------------------
// Edge scatter (identical to R5). One thread per (edge, k); 8 consecutive
// lanes share one edge -> broadcast edge loads, full-128B node_q gathers.
// DL pairs via shfl: even-k lanes issue one v4 RED covering two k's.
// DL RED issued BEFORE the Hamilton product (overlap LSU queue with FMAs).
// ---------------------------------------------------------------------------
__global__ void __launch_bounds__(256)
spt_edge_kernel(const float*  __restrict__ node_levels,
                const float4* __restrict__ node_q,
                const float4* __restrict__ edge_rel_q,
                const float*  __restrict__ edge_w,
                const int*    __restrict__ edge_src,
                const int*    __restrict__ edge_dst,
                long long EK)
{
    long long t = (long long)blockIdx.x * blockDim.x + threadIdx.x;
    bool active = (t < EK);
    long long tc = active ? t : 0;        // clamp for safe loads
    int e = (int)(tc >> 3);
    int k = (int)(tc & 7);

    int   s  = __ldg(edge_src + e);
    int   d  = __ldg(edge_dst + e);
    float w  = __ldg(edge_w + e);
    float4 rq = __ldg(edge_rel_q + e);

    int si = s * KDIM + k;
    float4 qs = __ldg(node_q + si);
    float  l  = __ldg(node_levels + si);

    float ee  = __expf(8.0f * w * l);     // exp_e (softmax shift cancels)
    float eel = ee * l;

    // Pair up DL values: even lane k takes lane k+1's {ee, eel}.
    float nee  = __shfl_down_sync(0xffffffffu, ee, 1);
    float neel = __shfl_down_sync(0xffffffffu, eel, 1);

    int di = d * KDIM + k;

    // Issue DL RED early (independent of the Hamilton product below).
    if (active && ((k & 1) == 0)) {
        float4* adl = (float4*)(g_accDL2 + di);  // 16B aligned (di even)
        asm volatile("red.global.add.v4.f32 [%0], {%1, %2, %3, %4};"
                     :: "l"(adl), "f"(ee), "f"(eel), "f"(nee), "f"(neel)
                     : "memory");
    }

    // Hamilton product rel_q (*) q_src ; storage order (w,x,y,z)
    float w1 = rq.x, x1 = rq.y, y1 = rq.z, z1 = rq.w;
    float w2 = qs.x, x2 = qs.y, y2 = qs.z, z2 = qs.w;
    float ow = w1*w2 - x1*x2 - y1*y2 - z1*z2;
    float ox = w1*x2 + x1*w2 + y1*z2 - z1*y2;
    float oy = w1*y2 - x1*z2 + y1*w2 + z1*x2;
    float oz = w1*z2 + x1*y2 - y1*x2 + z1*w2;

    if (active) {
        float4* aq = g_accQ4 + di;
        asm volatile("red.global.add.v4.f32 [%0], {%1, %2, %3, %4};"
                     :: "l"(aq), "f"(ee*ow), "f"(ee*ox), "f"(ee*oy), "f"(ee*oz)
                     : "memory");
    }
}

// ---------------------------------------------------------------------------
// Finalize (lean, R2-style): add self term, divide, L2-normalize, write.
// No re-zero here — accumulators are cleared by memsetAsync each replay.
// ---------------------------------------------------------------------------
__global__ void __launch_bounds__(256)
spt_final_kernel(const float* __restrict__ node_levels,
                 const float4* __restrict__ node_q,
                 float4* __restrict__ out_q,
                 float*  __restrict__ out_l,
                 int NK)
{
    int i = blockIdx.x * blockDim.x + threadIdx.x;
    if (i >= NK) return;

    float  l  = node_levels[i];
    float  es = __expf(8.0f * l);         // self term exp (w = 1)
    float4 q  = node_q[i];

    float2 dl = g_accDL2[i];
    float denom = dl.x + es;
    float suml  = dl.y + es * l;

    float4 a = g_accQ4[i];
    float qw = a.x + es * q.x;
    float qx = a.y + es * q.y;
    float qy = a.z + es * q.z;
    float qz = a.w + es * q.w;

    float inv = 1.0f / denom;
    qw *= inv; qx *= inv; qy *= inv; qz *= inv;

    float nrm = sqrtf(qw*qw + qx*qx + qy*qy + qz*qz);
    float r   = 1.0f / fmaxf(nrm, 1e-12f);
    out_q[i] = make_float4(qw * r, qx * r, qy * r, qz * r);
    out_l[i] = suml * inv;
}

// ---------------------------------------------------------------------------
// Launch. Inputs: 0 node_levels [N,K], 1 node_q [N,K,4], 2 edge_rel_q [E,4],
//                 3 edge_w [E], 4 edge_src [E], 5 edge_dst [E].
// Output: q [N,K,4] flattened, then out_levels [N,K].
// ---------------------------------------------------------------------------
extern "C" void kernel_launch(void* const* d_in, const int* in_sizes, int n_in,
                              void* d_out, int out_size)
{
    const float*  node_levels = (const float*) d_in[0];
    const float4* node_q      = (const float4*)d_in[1];
    const float4* edge_rel_q  = (const float4*)d_in[2];
    const float*  edge_w      = (const float*) d_in[3];
    const int*    edge_src    = (const int*)   d_in[4];
    const int*    edge_dst    = (const int*)   d_in[5];

    int NK = in_sizes[0];                 // N*K
    int E  = in_sizes[3];
    long long EK = (long long)E * KDIM;

    float4* out_q = (float4*)d_out;
    float*  out_l = (float*)d_out + (long long)NK * 4;

    // Zero the accumulators (graph-capturable async memsets).
    void* pQ = nullptr; void* pDL = nullptr;
    cudaGetSymbolAddress(&pQ,  g_accQ4);
    cudaGetSymbolAddress(&pDL, g_accDL2);
    cudaMemsetAsync(pQ,  0, (size_t)NK * sizeof(float4), 0);
    cudaMemsetAsync(pDL, 0, (size_t)NK * sizeof(float2), 0);

    const int TPB = 256;
    int grid_nk = (NK + TPB - 1) / TPB;
    int grid_ek = (int)((EK + TPB - 1) / TPB);

    spt_edge_kernel<<<grid_ek, TPB>>>(node_levels, node_q, edge_rel_q,
                                      edge_w, edge_src, edge_dst, EK);
    spt_final_kernel<<<grid_nk, TPB>>>(node_levels, node_q, out_q, out_l, NK);
}